// round 5
// baseline (speedup 1.0000x reference)
#include <cuda_runtime.h>
#include <math.h>
#include <stdint.h>

// Problem constants (fixed by setup_inputs)
#define G     8
#define HID   4000
#define Q     512
#define QG    64      // Q / G
#define LWIN  6       // L
#define INSZ  76      // QG + 2*L
#define STEPS 400
#define EPS   32
#define NHIST 64      // u_hist rows

#define NROWS (G * HID)          // 32000 weight rows
#define KPAD  4096               // padded row length (zeros beyond HID)
#define NSEG  16                 // 4096 / 256 segments per row
#define SEGC  256                // columns per segment
#define BX    74                 // blocks per group  (592 total = 4/SM exact wave)
#define CPG   500                // 8-row chunks per group

// Scratch: double-buffered hidden state, quantized+padded W_hh, per-row scales
__device__ float g_h[2][G * HID];
__device__ short g_Wq[(size_t)NROWS * KPAD];    // 262 MB int16 weights (padded)
__device__ float g_ds[NROWS];                   // dequant scale per row

// ---------------------------------------------------------------------------
// cp.async helpers (per-lane 16B copies)
// ---------------------------------------------------------------------------
__device__ __forceinline__ void cp16(uint32_t saddr, const void* gptr)
{
    asm volatile("cp.async.cg.shared.global [%0], [%1], 16;"
                 :: "r"(saddr), "l"(gptr));
}
__device__ __forceinline__ void cp_commit()
{
    asm volatile("cp.async.commit_group;");
}
__device__ __forceinline__ void cp_wait3()
{
    asm volatile("cp.async.wait_group 3;");
}

// ---------------------------------------------------------------------------
// Quantize W_hh rows to int16 (per-row absmax), write padded to KPAD cols.
// grid = NROWS/8, block = 256 (one row per warp).
// ---------------------------------------------------------------------------
__global__ void __launch_bounds__(256) quant_kernel(const float* __restrict__ W_hh)
{
    const int warp = threadIdx.x >> 5;
    const int lane = threadIdx.x & 31;
    const int row  = blockIdx.x * 8 + warp;

    const float4* w4 = (const float4*)(W_hh + (size_t)row * HID);

    float m = 0.0f;
    for (int j = lane; j < HID / 4; j += 32) {
        float4 v = w4[j];
        m = fmaxf(m, fmaxf(fmaxf(fabsf(v.x), fabsf(v.y)),
                           fmaxf(fabsf(v.z), fabsf(v.w))));
    }
    #pragma unroll
    for (int off = 16; off; off >>= 1)
        m = fmaxf(m, __shfl_xor_sync(0xffffffffu, m, off));

    const float qs = (m > 0.0f) ? (32767.0f / m) : 0.0f;
    if (lane == 0)
        g_ds[row] = (m > 0.0f) ? (m / 32767.0f) : 0.0f;

    uint2* dst = (uint2*)(g_Wq + (size_t)row * KPAD);
    for (int j = lane; j < HID / 4; j += 32) {
        float4 v = w4[j];
        int s0 = __float2int_rn(fminf(fmaxf(v.x * qs, -32767.0f), 32767.0f));
        int s1 = __float2int_rn(fminf(fmaxf(v.y * qs, -32767.0f), 32767.0f));
        int s2 = __float2int_rn(fminf(fmaxf(v.z * qs, -32767.0f), 32767.0f));
        int s3 = __float2int_rn(fminf(fmaxf(v.w * qs, -32767.0f), 32767.0f));
        uint2 p;
        p.x = (s0 & 0xffff) | (s1 << 16);
        p.y = (s2 & 0xffff) | (s3 << 16);
        dst[j] = p;
    }
    // zero the pad
    uint2 z; z.x = 0; z.y = 0;
    for (int j = HID / 4 + lane; j < KPAD / 4; j += 32)
        dst[j] = z;
}

// 8 int16 weights (one int4) against 8 h values (two float4)
__device__ __forceinline__ void dotq(int4 w, float4 ha, float4 hb, float& acc)
{
    acc += (float)((short)w.x) * ha.x + (float)(w.x >> 16) * ha.y;
    acc += (float)((short)w.y) * ha.z + (float)(w.y >> 16) * ha.w;
    acc += (float)((short)w.z) * hb.x + (float)(w.z >> 16) * hb.y;
    acc += (float)((short)w.w) * hb.z + (float)(w.w >> 16) * hb.w;
}

// ---------------------------------------------------------------------------
// One ESN step with int16 W_hh and a per-warp 4-stage cp.async pipeline.
//   h_out = 0.4*h_in + 0.6*tanh(ds*(Wq@h_in) + W_in@ug)
// grid = (74, G) = 592 blocks (exactly 4/SM), block = 256.
// Block bx handles 8-row chunks {bx, bx+74, ...} (6 or 7 chunks).
// Within a chunk, warp w owns row chunk*8+w. Lane j prefetches/consumes its
// private 16 B of each 256-col segment -> no intra-warp synchronization.
// ---------------------------------------------------------------------------
__global__ void __launch_bounds__(256) step_kernel(
    const float* __restrict__ W_in,   // [G, HID, INSZ]
    const float* __restrict__ u,      // [Q]
    const float* __restrict__ h_in,   // [G, HID]
    float*       __restrict__ h_out)  // [G, HID]
{
    __shared__ __align__(16) float sh_h[KPAD];
    __shared__ __align__(16) short sh_w[8 * 4 * SEGC];   // [warp][stage][256]
    __shared__ float sh_u[INSZ];

    const int g   = blockIdx.y;
    const int bx  = blockIdx.x;
    const int tid = threadIdx.x;

    for (int i = tid; i < KPAD; i += 256)
        sh_h[i] = (i < HID) ? h_in[g * HID + i] : 0.0f;
    if (tid < INSZ)
        sh_u[tid] = u[(g * QG - LWIN + tid + Q) & (Q - 1)];  // periodic window
    __syncthreads();

    const int warp = tid >> 5;
    const int lane = tid & 31;

    const int nk    = (bx < CPG - BX * (CPG / BX)) ? (CPG / BX + 1) : (CPG / BX); // 7 or 6
    const int total = nk * NSEG;

    const int r0 = bx * 8 + warp;                 // row for chunk k: r0 + 592*k
    short* sw = sh_w + warp * (4 * SEGC);         // this warp's 4 stages
    const uint32_t sbase =
        (uint32_t)__cvta_generic_to_shared(sw) + (uint32_t)lane * 16;

    // issue seg t: chunk k = t>>4, seg = t&15, stage = t&3
    auto src = [&](int t) -> const void* {
        const size_t row = (size_t)g * HID + r0 + 592 * (t >> 4);
        return (const void*)(g_Wq + row * KPAD + (t & 15) * SEGC + lane * 8);
    };

    // prologue: stages 0..2
    #pragma unroll
    for (int t = 0; t < 3; ++t) {
        cp16(sbase + (uint32_t)(t & 3) * (SEGC * 2), src(t));
        cp_commit();
    }

    float acc = 0.0f;
    for (int t = 0; t < total; ++t) {
        if (t + 3 < total)
            cp16(sbase + (uint32_t)((t + 3) & 3) * (SEGC * 2), src(t + 3));
        cp_commit();
        cp_wait3();                               // seg t resident

        const int4  w  = *(const int4*)(sw + (t & 3) * SEGC + lane * 8);
        const int   c0 = (t & 15) * SEGC + lane * 8;
        const float4 ha = *(const float4*)&sh_h[c0];
        const float4 hb = *(const float4*)&sh_h[c0 + 4];
        dotq(w, ha, hb, acc);

        if ((t & 15) == 15) {                     // row finished
            const int r    = r0 + 592 * (t >> 4); // local row in group
            const int grow = g * HID + r;
            acc *= g_ds[grow];

            const float* wi = W_in + (size_t)grow * INSZ;
            #pragma unroll
            for (int o = lane; o < INSZ; o += 32)
                acc += wi[o] * sh_u[o];

            #pragma unroll
            for (int off = 16; off; off >>= 1)
                acc += __shfl_xor_sync(0xffffffffu, acc, off);

            if (lane == 0)
                h_out[grow] = 0.4f * sh_h[r] + 0.6f * tanhf(acc);
            acc = 0.0f;
        }
    }
}

// ---------------------------------------------------------------------------
// Readout: y[g*64+o] = W_out[g,o,:] . [h ; h*h]   (fp32, ~2 us)
// ---------------------------------------------------------------------------
__global__ void __launch_bounds__(256) readout_kernel(
    const float* __restrict__ W_out,  // [G, QG, 2*HID]
    const float* __restrict__ h,      // [G, HID]
    float*       __restrict__ y)      // [Q]
{
    __shared__ __align__(16) float sh_h[HID];
    __shared__ float sh_red[8];

    const int g   = blockIdx.y;
    const int o   = blockIdx.x;
    const int tid = threadIdx.x;

    for (int i = tid; i < HID; i += 256)
        sh_h[i] = h[g * HID + i];
    __syncthreads();

    const float4* sh4 = (const float4*)sh_h;
    const float4* w4  = (const float4*)(W_out + ((size_t)g * QG + o) * (2 * HID));

    float acc = 0.0f;
    #pragma unroll 2
    for (int j = tid; j < HID / 4; j += 256) {
        float4 wv = w4[j];
        float4 hv = sh4[j];
        acc += wv.x * hv.x + wv.y * hv.y + wv.z * hv.z + wv.w * hv.w;
    }
    #pragma unroll 2
    for (int j = tid; j < HID / 4; j += 256) {
        float4 wv = w4[HID / 4 + j];
        float4 hv = sh4[j];
        acc += wv.x * (hv.x * hv.x) + wv.y * (hv.y * hv.y)
             + wv.z * (hv.z * hv.z) + wv.w * (hv.w * hv.w);
    }

    const int warp = tid >> 5;
    const int lane = tid & 31;
    #pragma unroll
    for (int off = 16; off; off >>= 1)
        acc += __shfl_xor_sync(0xffffffffu, acc, off);
    if (lane == 0) sh_red[warp] = acc;
    __syncthreads();
    if (warp == 0) {
        float v = (lane < 8) ? sh_red[lane] : 0.0f;
        #pragma unroll
        for (int off = 4; off; off >>= 1)
            v += __shfl_xor_sync(0xffffffffu, v, off);
        if (lane == 0) y[g * QG + o] = v;
    }
}

// ---------------------------------------------------------------------------
// Launch sequence: quantize, 32 warmup steps, 400 (step, readout) pairs.
// ---------------------------------------------------------------------------
extern "C" void kernel_launch(void* const* d_in, const int* in_sizes, int n_in,
                              void* d_out, int out_size)
{
    const float* u_hist = (const float*)d_in[0];   // [64, 512]
    const float* W_in   = (const float*)d_in[1];   // [8, 4000, 76]
    const float* W_hh   = (const float*)d_in[2];   // [8, 4000, 4000]
    const float* W_out  = (const float*)d_in[3];   // [8, 64, 8000]
    float*       out    = (float*)d_out;           // [400, 512]

    float* hbase = nullptr;
    cudaGetSymbolAddress((void**)&hbase, g_h);
    cudaMemsetAsync(hbase, 0, sizeof(float) * G * HID, 0);

    quant_kernel<<<NROWS / 8, 256>>>(W_hh);

    const dim3 sgrid(BX, G);       // 592 blocks = exactly 4/SM
    const dim3 rgrid(QG, G);       // 512 blocks

    float* hb[2] = { hbase, hbase + G * HID };

    for (int t = 0; t < EPS; ++t) {
        const float* u = u_hist + (size_t)(NHIST - EPS + t) * Q;
        step_kernel<<<sgrid, 256>>>(W_in, u, hb[t & 1], hb[(t + 1) & 1]);
    }

    for (int s = 0; s < STEPS; ++s) {
        const float* u = (s == 0) ? (u_hist + (size_t)(NHIST - 1) * Q)
                                  : (out + (size_t)(s - 1) * Q);
        step_kernel<<<sgrid, 256>>>(W_in, u, hb[s & 1], hb[(s + 1) & 1]);
        readout_kernel<<<rgrid, 256>>>(W_out, hb[(s + 1) & 1], out + (size_t)s * Q);
    }
}

// round 6
// speedup vs baseline: 1.1441x; 1.1441x over previous
#include <cuda_runtime.h>
#include <math.h>
#include <stdint.h>

// Problem constants (fixed by setup_inputs)
#define G     8
#define HID   4000
#define Q     512
#define QG    64      // Q / G
#define LWIN  6       // L
#define INSZ  76      // QG + 2*L
#define STEPS 400
#define EPS   32
#define NHIST 64      // u_hist rows

#define NROWS (G * HID)          // 32000 weight rows
#define KPAD  4096               // padded row length (zeros beyond HID)
#define BXG   18                 // blocks per group (grid 144 = 1/SM)
#define TPG   500                // 8-row tiles per group
#define TILE_BYTES 65536         // 8 rows * 4096 shorts * 2B
#define NSTAGE 3

// smem layout offsets (bytes)
#define SM_H    0                 // KPAD floats = 16384
#define SM_U    16384             // 128 floats  = 512
#define SM_MBAR 16896             // 3 * 8 = 24 (padded)
#define SM_BUF  17024             // 3 * 65536
#define SM_TOTAL (SM_BUF + NSTAGE * TILE_BYTES)   // 213632

// Scratch: double-buffered hidden state, quantized+padded W_hh, per-row scales
__device__ float g_h[2][G * HID];
__device__ short g_Wq[(size_t)NROWS * KPAD];    // 262 MB int16 weights (padded)
__device__ float g_ds[NROWS];                   // dequant scale per row

// ---------------------------------------------------------------------------
// async-bulk helpers
// ---------------------------------------------------------------------------
__device__ __forceinline__ void mbar_init(uint32_t mbar, uint32_t count)
{
    asm volatile("mbarrier.init.shared.b64 [%0], %1;" :: "r"(mbar), "r"(count) : "memory");
}
__device__ __forceinline__ void mbar_expect_tx(uint32_t mbar, uint32_t bytes)
{
    asm volatile("mbarrier.arrive.expect_tx.shared.b64 _, [%0], %1;"
                 :: "r"(mbar), "r"(bytes) : "memory");
}
__device__ __forceinline__ void bulk_g2s(uint32_t dst, const void* src,
                                         uint32_t bytes, uint32_t mbar)
{
    asm volatile("cp.async.bulk.shared::cta.global.mbarrier::complete_tx::bytes "
                 "[%0], [%1], %2, [%3];"
                 :: "r"(dst), "l"(src), "r"(bytes), "r"(mbar) : "memory");
}
__device__ __forceinline__ void mbar_wait(uint32_t mbar, uint32_t parity)
{
    asm volatile(
        "{\n\t"
        ".reg .pred P;\n\t"
        "WAIT_%=:\n\t"
        "mbarrier.try_wait.parity.shared.b64 P, [%0], %1, 0x989680;\n\t"
        "@P bra DONE_%=;\n\t"
        "bra WAIT_%=;\n\t"
        "DONE_%=:\n\t"
        "}"
        :: "r"(mbar), "r"(parity) : "memory");
}

// ---------------------------------------------------------------------------
// Quantize W_hh rows to int16 (per-row absmax), write padded to KPAD cols.
// ---------------------------------------------------------------------------
__global__ void __launch_bounds__(256) quant_kernel(const float* __restrict__ W_hh)
{
    const int warp = threadIdx.x >> 5;
    const int lane = threadIdx.x & 31;
    const int row  = blockIdx.x * 8 + warp;

    const float4* w4 = (const float4*)(W_hh + (size_t)row * HID);

    float m = 0.0f;
    for (int j = lane; j < HID / 4; j += 32) {
        float4 v = w4[j];
        m = fmaxf(m, fmaxf(fmaxf(fabsf(v.x), fabsf(v.y)),
                           fmaxf(fabsf(v.z), fabsf(v.w))));
    }
    #pragma unroll
    for (int off = 16; off; off >>= 1)
        m = fmaxf(m, __shfl_xor_sync(0xffffffffu, m, off));

    const float qs = (m > 0.0f) ? (32767.0f / m) : 0.0f;
    if (lane == 0)
        g_ds[row] = (m > 0.0f) ? (m / 32767.0f) : 0.0f;

    uint2* dst = (uint2*)(g_Wq + (size_t)row * KPAD);
    for (int j = lane; j < HID / 4; j += 32) {
        float4 v = w4[j];
        int s0 = __float2int_rn(fminf(fmaxf(v.x * qs, -32767.0f), 32767.0f));
        int s1 = __float2int_rn(fminf(fmaxf(v.y * qs, -32767.0f), 32767.0f));
        int s2 = __float2int_rn(fminf(fmaxf(v.z * qs, -32767.0f), 32767.0f));
        int s3 = __float2int_rn(fminf(fmaxf(v.w * qs, -32767.0f), 32767.0f));
        uint2 p;
        p.x = (s0 & 0xffff) | (s1 << 16);
        p.y = (s2 & 0xffff) | (s3 << 16);
        dst[j] = p;
    }
    uint2 z; z.x = 0; z.y = 0;
    for (int j = HID / 4 + lane; j < KPAD / 4; j += 32)
        dst[j] = z;
}

// 8 int16 weights (one int4) against 8 h values (two float4)
__device__ __forceinline__ void dotq(int4 w, float4 ha, float4 hb, float& acc)
{
    acc += (float)((short)w.x) * ha.x + (float)(w.x >> 16) * ha.y;
    acc += (float)((short)w.y) * ha.z + (float)(w.y >> 16) * ha.w;
    acc += (float)((short)w.z) * hb.x + (float)(w.z >> 16) * hb.y;
    acc += (float)((short)w.w) * hb.z + (float)(w.w >> 16) * hb.w;
}

// ---------------------------------------------------------------------------
// One ESN step. W_hh streamed via cp.async.bulk (TMA path, bypasses the
// per-SM LDG queue that capped previous rounds at ~4.6 TB/s).
// grid = (18, G) = 144 blocks = 1/SM. block = 256 (8 warps).
// Block bx of group g handles 8-row tiles {bx, bx+18, ...} < 500.
// 3-stage 64KB smem pipeline; warp w computes row w of each tile; the lane's
// 128 h-values live in registers.
// ---------------------------------------------------------------------------
__global__ void __launch_bounds__(256, 1) step_kernel(
    const float* __restrict__ W_in,   // [G, HID, INSZ]
    const float* __restrict__ u,      // [Q]
    const float* __restrict__ h_in,   // [G, HID]
    float*       __restrict__ h_out)  // [G, HID]
{
    extern __shared__ __align__(128) char smem[];
    float* sh_h = (float*)(smem + SM_H);
    float* sh_u = (float*)(smem + SM_U);

    const int g   = blockIdx.y;
    const int bx  = blockIdx.x;
    const int tid = threadIdx.x;

    const uint32_t smem_base = (uint32_t)__cvta_generic_to_shared(smem);
    const uint32_t mb        = smem_base + SM_MBAR;

    for (int i = tid; i < KPAD; i += 256)
        sh_h[i] = (i < HID) ? h_in[g * HID + i] : 0.0f;
    if (tid < INSZ)
        sh_u[tid] = u[(g * QG - LWIN + tid + Q) & (Q - 1)];  // periodic window

    const int ntiles = (TPG - bx + BXG - 1) / BXG;   // 27 or 28

    if (tid == 0) {
        #pragma unroll
        for (int s = 0; s < NSTAGE; ++s)
            mbar_init(mb + s * 8, 1);
        asm volatile("fence.proxy.async.shared::cta;" ::: "memory");
    }
    __syncthreads();

    if (tid == 0) {
        #pragma unroll
        for (int i = 0; i < NSTAGE; ++i) {
            if (i < ntiles) {
                const int tile = bx + BXG * i;
                const void* src = g_Wq + ((size_t)g * HID + (size_t)tile * 8) * KPAD;
                mbar_expect_tx(mb + i * 8, TILE_BYTES);
                bulk_g2s(smem_base + SM_BUF + i * TILE_BYTES, src, TILE_BYTES, mb + i * 8);
            }
        }
    }

    const int warp = tid >> 5;
    const int lane = tid & 31;

    // preload this lane's h slice: cols j*256 + lane*8 .. +7, j = 0..15
    float4 hreg[32];
    const float4* sh4 = (const float4*)sh_h;
    #pragma unroll
    for (int j = 0; j < 16; ++j) {
        hreg[2 * j]     = sh4[j * 64 + lane * 2];
        hreg[2 * j + 1] = sh4[j * 64 + lane * 2 + 1];
    }

    for (int i = 0; i < ntiles; ++i) {
        const int s    = i % NSTAGE;
        const int tile = bx + BXG * i;

        mbar_wait(mb + s * 8, (uint32_t)((i / NSTAGE) & 1));

        // warp w -> row tile*8 + w of group g; 4096 shorts = 512 int4
        const int4* w4 =
            (const int4*)(smem + SM_BUF + s * TILE_BYTES) + warp * 512;

        float a0 = 0.0f, a1 = 0.0f, a2 = 0.0f, a3 = 0.0f;
        #pragma unroll
        for (int j = 0; j < 16; ++j) {
            int4 w = w4[j * 32 + lane];
            float& acc = (j & 3) == 0 ? a0 : (j & 3) == 1 ? a1 : (j & 3) == 2 ? a2 : a3;
            dotq(w, hreg[2 * j], hreg[2 * j + 1], acc);
        }
        float acc = (a0 + a1) + (a2 + a3);

        const int r    = tile * 8 + warp;       // row within group
        const int grow = g * HID + r;
        acc *= g_ds[grow];

        const float* wi = W_in + (size_t)grow * INSZ;
        #pragma unroll
        for (int o = lane; o < INSZ; o += 32)
            acc += wi[o] * sh_u[o];

        #pragma unroll
        for (int off = 16; off; off >>= 1)
            acc += __shfl_xor_sync(0xffffffffu, acc, off);

        if (lane == 0)
            h_out[grow] = 0.4f * sh_h[r] + 0.6f * tanhf(acc);

        __syncthreads();   // everyone done with buf[s] before tid0 reuses it
        if (tid == 0 && i + NSTAGE < ntiles) {
            const int nt = bx + BXG * (i + NSTAGE);
            const void* src = g_Wq + ((size_t)g * HID + (size_t)nt * 8) * KPAD;
            mbar_expect_tx(mb + s * 8, TILE_BYTES);
            bulk_g2s(smem_base + SM_BUF + s * TILE_BYTES, src, TILE_BYTES, mb + s * 8);
        }
    }
}

// ---------------------------------------------------------------------------
// Readout: y[g*64+o] = W_out[g,o,:] . [h ; h*h]   (fp32, ~2.5 us)
// ---------------------------------------------------------------------------
__global__ void __launch_bounds__(256) readout_kernel(
    const float* __restrict__ W_out,  // [G, QG, 2*HID]
    const float* __restrict__ h,      // [G, HID]
    float*       __restrict__ y)      // [Q]
{
    __shared__ __align__(16) float sh_h[HID];
    __shared__ float sh_red[8];

    const int g   = blockIdx.y;
    const int o   = blockIdx.x;
    const int tid = threadIdx.x;

    for (int i = tid; i < HID; i += 256)
        sh_h[i] = h[g * HID + i];
    __syncthreads();

    const float4* sh4 = (const float4*)sh_h;
    const float4* w4  = (const float4*)(W_out + ((size_t)g * QG + o) * (2 * HID));

    float acc = 0.0f;
    #pragma unroll 2
    for (int j = tid; j < HID / 4; j += 256) {
        float4 wv = w4[j];
        float4 hv = sh4[j];
        acc += wv.x * hv.x + wv.y * hv.y + wv.z * hv.z + wv.w * hv.w;
    }
    #pragma unroll 2
    for (int j = tid; j < HID / 4; j += 256) {
        float4 wv = w4[HID / 4 + j];
        float4 hv = sh4[j];
        acc += wv.x * (hv.x * hv.x) + wv.y * (hv.y * hv.y)
             + wv.z * (hv.z * hv.z) + wv.w * (hv.w * hv.w);
    }

    const int warp = tid >> 5;
    const int lane = tid & 31;
    #pragma unroll
    for (int off = 16; off; off >>= 1)
        acc += __shfl_xor_sync(0xffffffffu, acc, off);
    if (lane == 0) sh_red[warp] = acc;
    __syncthreads();
    if (warp == 0) {
        float v = (lane < 8) ? sh_red[lane] : 0.0f;
        #pragma unroll
        for (int off = 4; off; off >>= 1)
            v += __shfl_xor_sync(0xffffffffu, v, off);
        if (lane == 0) y[g * QG + o] = v;
    }
}

// ---------------------------------------------------------------------------
// Launch sequence: quantize, 32 warmup steps, 400 (step, readout) pairs.
// ---------------------------------------------------------------------------
extern "C" void kernel_launch(void* const* d_in, const int* in_sizes, int n_in,
                              void* d_out, int out_size)
{
    const float* u_hist = (const float*)d_in[0];   // [64, 512]
    const float* W_in   = (const float*)d_in[1];   // [8, 4000, 76]
    const float* W_hh   = (const float*)d_in[2];   // [8, 4000, 4000]
    const float* W_out  = (const float*)d_in[3];   // [8, 64, 8000]
    float*       out    = (float*)d_out;           // [400, 512]

    float* hbase = nullptr;
    cudaGetSymbolAddress((void**)&hbase, g_h);
    cudaMemsetAsync(hbase, 0, sizeof(float) * G * HID, 0);

    cudaFuncSetAttribute(step_kernel,
                         cudaFuncAttributeMaxDynamicSharedMemorySize, SM_TOTAL);

    quant_kernel<<<NROWS / 8, 256>>>(W_hh);

    const dim3 sgrid(BXG, G);      // 144 blocks = 1/SM
    const dim3 rgrid(QG, G);       // 512 blocks

    float* hb[2] = { hbase, hbase + G * HID };

    for (int t = 0; t < EPS; ++t) {
        const float* u = u_hist + (size_t)(NHIST - EPS + t) * Q;
        step_kernel<<<sgrid, 256, SM_TOTAL>>>(W_in, u, hb[t & 1], hb[(t + 1) & 1]);
    }

    for (int s = 0; s < STEPS; ++s) {
        const float* u = (s == 0) ? (u_hist + (size_t)(NHIST - 1) * Q)
                                  : (out + (size_t)(s - 1) * Q);
        step_kernel<<<sgrid, 256, SM_TOTAL>>>(W_in, u, hb[s & 1], hb[(s + 1) & 1]);
        readout_kernel<<<rgrid, 256>>>(W_out, hb[(s + 1) & 1], out + (size_t)s * Q);
    }
}

// round 7
// speedup vs baseline: 1.2001x; 1.0489x over previous
#include <cuda_runtime.h>
#include <math.h>
#include <stdint.h>

// Problem constants (fixed by setup_inputs)
#define G     8
#define HID   4000
#define Q     512
#define QG    64      // Q / G
#define LWIN  6       // L
#define INSZ  76      // QG + 2*L
#define STEPS 400
#define EPS   32
#define NHIST 64      // u_hist rows

#define NROWS (G * HID)          // 32000 W_hh rows
#define KPAD  4096               // padded row length (zeros beyond HID)
#define BXG   18                 // blocks per group (grid 144 = 1/SM)
#define TPG   500                // 8-row tiles per group
#define TILE_BYTES 65536         // 8 rows * 4096 shorts * 2B
#define NSTAGE 3
#define NTHREADS 288             // 8 consumer warps + 1 producer warp

#define OROWS (G * QG)           // 512 W_out rows
#define OWID  8000               // 2*HID

// smem layout offsets (bytes)
#define SM_H    0                 // KPAD floats = 16384
#define SM_U    16384             // INSZ floats (padded to 512)
#define SM_MBAR 16896             // full[3] @ +0, empty[3] @ +24
#define SM_BUF  17024             // 3 * 65536
#define SM_TOTAL (SM_BUF + NSTAGE * TILE_BYTES)   // 213632

// Scratch
__device__ float g_h[2][G * HID];
__device__ short g_Wq[(size_t)NROWS * KPAD];    // 262 MB int16 W_hh (padded)
__device__ float g_ds[NROWS];                   // W_hh dequant scale per row
__device__ short g_Wo[(size_t)OROWS * OWID];    // 8 MB int16 W_out
__device__ float g_dso[OROWS];                  // W_out dequant scale per row

// ---------------------------------------------------------------------------
// async-bulk / mbarrier helpers
// ---------------------------------------------------------------------------
__device__ __forceinline__ void mbar_init(uint32_t mbar, uint32_t count)
{
    asm volatile("mbarrier.init.shared.b64 [%0], %1;" :: "r"(mbar), "r"(count) : "memory");
}
__device__ __forceinline__ void mbar_expect_tx(uint32_t mbar, uint32_t bytes)
{
    asm volatile("mbarrier.arrive.expect_tx.shared.b64 _, [%0], %1;"
                 :: "r"(mbar), "r"(bytes) : "memory");
}
__device__ __forceinline__ void mbar_arrive(uint32_t mbar)
{
    asm volatile("mbarrier.arrive.shared.b64 _, [%0];" :: "r"(mbar) : "memory");
}
__device__ __forceinline__ void bulk_g2s(uint32_t dst, const void* src,
                                         uint32_t bytes, uint32_t mbar)
{
    asm volatile("cp.async.bulk.shared::cta.global.mbarrier::complete_tx::bytes "
                 "[%0], [%1], %2, [%3];"
                 :: "r"(dst), "l"(src), "r"(bytes), "r"(mbar) : "memory");
}
__device__ __forceinline__ void mbar_wait(uint32_t mbar, uint32_t parity)
{
    asm volatile(
        "{\n\t"
        ".reg .pred P;\n\t"
        "WAIT_%=:\n\t"
        "mbarrier.try_wait.parity.shared.b64 P, [%0], %1, 0x989680;\n\t"
        "@P bra DONE_%=;\n\t"
        "bra WAIT_%=;\n\t"
        "DONE_%=:\n\t"
        "}"
        :: "r"(mbar), "r"(parity) : "memory");
}

// ---------------------------------------------------------------------------
// Generic per-row absmax int16 quantizer: rows of `width` floats -> shorts
// (dst row stride = wpad, zero-padded). One row per warp.
// ---------------------------------------------------------------------------
__global__ void __launch_bounds__(256) quant_rows_kernel(
    const float* __restrict__ W, short* __restrict__ dst_base,
    float* __restrict__ ds, int width, int wpad)
{
    const int warp = threadIdx.x >> 5;
    const int lane = threadIdx.x & 31;
    const int row  = blockIdx.x * 8 + warp;

    const float4* w4 = (const float4*)(W + (size_t)row * width);
    const int nf4 = width / 4;

    float m = 0.0f;
    for (int j = lane; j < nf4; j += 32) {
        float4 v = w4[j];
        m = fmaxf(m, fmaxf(fmaxf(fabsf(v.x), fabsf(v.y)),
                           fmaxf(fabsf(v.z), fabsf(v.w))));
    }
    #pragma unroll
    for (int off = 16; off; off >>= 1)
        m = fmaxf(m, __shfl_xor_sync(0xffffffffu, m, off));

    const float qs = (m > 0.0f) ? (32767.0f / m) : 0.0f;
    if (lane == 0)
        ds[row] = (m > 0.0f) ? (m / 32767.0f) : 0.0f;

    uint2* dst = (uint2*)(dst_base + (size_t)row * wpad);
    for (int j = lane; j < nf4; j += 32) {
        float4 v = w4[j];
        int s0 = __float2int_rn(fminf(fmaxf(v.x * qs, -32767.0f), 32767.0f));
        int s1 = __float2int_rn(fminf(fmaxf(v.y * qs, -32767.0f), 32767.0f));
        int s2 = __float2int_rn(fminf(fmaxf(v.z * qs, -32767.0f), 32767.0f));
        int s3 = __float2int_rn(fminf(fmaxf(v.w * qs, -32767.0f), 32767.0f));
        uint2 p;
        p.x = (s0 & 0xffff) | (s1 << 16);
        p.y = (s2 & 0xffff) | (s3 << 16);
        dst[j] = p;
    }
    uint2 z; z.x = 0; z.y = 0;
    for (int j = nf4 + lane; j < wpad / 4; j += 32)
        dst[j] = z;
}

// 8 int16 weights (one int4) against 8 h values (two float4)
__device__ __forceinline__ void dotq(int4 w, float4 ha, float4 hb, float& acc)
{
    acc += (float)((short)w.x) * ha.x + (float)(w.x >> 16) * ha.y;
    acc += (float)((short)w.y) * ha.z + (float)(w.y >> 16) * ha.w;
    acc += (float)((short)w.z) * hb.x + (float)(w.z >> 16) * hb.y;
    acc += (float)((short)w.w) * hb.z + (float)(w.w >> 16) * hb.w;
}

// ---------------------------------------------------------------------------
// One ESN step. W_hh streamed via cp.async.bulk with a decoupled
// producer-warp / consumer-warps mbarrier ring (no __syncthreads in loop).
// grid = (18, G) = 144 blocks = 1/SM. block = 288 (8 consumers + 1 producer).
// ---------------------------------------------------------------------------
__global__ void __launch_bounds__(NTHREADS, 1) step_kernel(
    const float* __restrict__ W_in,   // [G, HID, INSZ]
    const float* __restrict__ u,      // [Q]
    const float* __restrict__ h_in,   // [G, HID]
    float*       __restrict__ h_out)  // [G, HID]
{
    extern __shared__ __align__(128) char smem[];
    float* sh_h = (float*)(smem + SM_H);
    float* sh_u = (float*)(smem + SM_U);

    const int g   = blockIdx.y;
    const int bx  = blockIdx.x;
    const int tid = threadIdx.x;

    const uint32_t smem_base = (uint32_t)__cvta_generic_to_shared(smem);
    const uint32_t mb_full   = smem_base + SM_MBAR;        // 3 x 8B
    const uint32_t mb_empty  = smem_base + SM_MBAR + 24;   // 3 x 8B

    for (int i = tid; i < KPAD; i += NTHREADS)
        sh_h[i] = (i < HID) ? h_in[g * HID + i] : 0.0f;
    if (tid < INSZ)
        sh_u[tid] = u[(g * QG - LWIN + tid + Q) & (Q - 1)];  // periodic window

    if (tid == 0) {
        #pragma unroll
        for (int s = 0; s < NSTAGE; ++s) {
            mbar_init(mb_full + s * 8, 1);
            mbar_init(mb_empty + s * 8, 8);
        }
        asm volatile("fence.proxy.async.shared::cta;" ::: "memory");
    }
    __syncthreads();

    const int ntiles = (TPG - bx + BXG - 1) / BXG;   // 27 or 28
    const int warp = tid >> 5;
    const int lane = tid & 31;

    if (warp == 8) {
        // ---------------- producer ----------------
        if (lane == 0) {
            int st = 0, ph = 1;          // phase=1: first 3 empty-waits pass
            for (int i = 0; i < ntiles; ++i) {
                mbar_wait(mb_empty + st * 8, (uint32_t)ph);
                const int tile = bx + BXG * i;
                const void* src =
                    g_Wq + ((size_t)g * HID + (size_t)tile * 8) * KPAD;
                mbar_expect_tx(mb_full + st * 8, TILE_BYTES);
                bulk_g2s(smem_base + SM_BUF + st * TILE_BYTES, src,
                         TILE_BYTES, mb_full + st * 8);
                if (++st == NSTAGE) { st = 0; ph ^= 1; }
            }
        }
        return;
    }

    // ---------------- consumers (warps 0..7) ----------------
    // preload this lane's h slice: cols j*256 + lane*8 .. +7, j = 0..15
    float4 hreg[32];
    const float4* sh4 = (const float4*)sh_h;
    #pragma unroll
    for (int j = 0; j < 16; ++j) {
        hreg[2 * j]     = sh4[j * 64 + lane * 2];
        hreg[2 * j + 1] = sh4[j * 64 + lane * 2 + 1];
    }

    int st = 0, ph = 0;
    for (int i = 0; i < ntiles; ++i) {
        const int tile = bx + BXG * i;

        mbar_wait(mb_full + st * 8, (uint32_t)ph);

        // warp w -> row tile*8 + w; 4096 shorts = 512 int4
        const int4* w4 =
            (const int4*)(smem + SM_BUF + st * TILE_BYTES) + warp * 512;

        float a0 = 0.0f, a1 = 0.0f, a2 = 0.0f, a3 = 0.0f;
        #pragma unroll
        for (int j = 0; j < 16; ++j) {
            int4 w = w4[j * 32 + lane];
            float& acc = (j & 3) == 0 ? a0 : (j & 3) == 1 ? a1 : (j & 3) == 2 ? a2 : a3;
            dotq(w, hreg[2 * j], hreg[2 * j + 1], acc);
        }
        float acc = (a0 + a1) + (a2 + a3);     // depends on all 16 loads

        if (lane == 0)
            mbar_arrive(mb_empty + st * 8);    // buffer free; refill overlaps epilogue

        const int r    = tile * 8 + warp;      // row within group
        const int grow = g * HID + r;
        acc *= g_ds[grow];

        const float* wi = W_in + (size_t)grow * INSZ;
        #pragma unroll
        for (int o = lane; o < INSZ; o += 32)
            acc += wi[o] * sh_u[o];

        #pragma unroll
        for (int off = 16; off; off >>= 1)
            acc += __shfl_xor_sync(0xffffffffu, acc, off);

        if (lane == 0)
            h_out[grow] = 0.4f * sh_h[r] + 0.6f * tanhf(acc);

        if (++st == NSTAGE) { st = 0; ph ^= 1; }
    }
}

// ---------------------------------------------------------------------------
// Readout with int16 W_out: y[g*64+o] = dso * (Wo[g,o,:] . [h ; h*h])
// grid = (QG, G), block = 256. One block per output element.
// h staging is L2-served (128 KB working set); DRAM traffic is the 8 MB Wo.
// ---------------------------------------------------------------------------
__global__ void __launch_bounds__(256) readout_kernel(
    const float* __restrict__ h,      // [G, HID]
    float*       __restrict__ y)      // [Q]
{
    __shared__ __align__(16) float sh_h[HID];
    __shared__ float sh_red[8];

    const int g   = blockIdx.y;
    const int o   = blockIdx.x;
    const int tid = threadIdx.x;

    for (int i = tid; i < HID; i += 256)
        sh_h[i] = h[g * HID + i];
    __syncthreads();

    const float4* sh4 = (const float4*)sh_h;
    const int row = g * QG + o;
    const int4* w4 = (const int4*)(g_Wo + (size_t)row * OWID);   // 1000 int4

    float acc = 0.0f;
    // h part: int4 j covers cols 8j..8j+7  (j < 500)
    #pragma unroll 2
    for (int j = tid; j < HID / 8; j += 256) {
        int4 w = w4[j];
        dotq(w, sh4[2 * j], sh4[2 * j + 1], acc);
    }
    // h^2 part
    #pragma unroll 2
    for (int j = tid; j < HID / 8; j += 256) {
        int4 w = w4[HID / 8 + j];
        float4 ha = sh4[2 * j], hb = sh4[2 * j + 1];
        ha.x *= ha.x; ha.y *= ha.y; ha.z *= ha.z; ha.w *= ha.w;
        hb.x *= hb.x; hb.y *= hb.y; hb.z *= hb.z; hb.w *= hb.w;
        dotq(w, ha, hb, acc);
    }

    const int warp = tid >> 5;
    const int lane = tid & 31;
    #pragma unroll
    for (int off = 16; off; off >>= 1)
        acc += __shfl_xor_sync(0xffffffffu, acc, off);
    if (lane == 0) sh_red[warp] = acc;
    __syncthreads();
    if (warp == 0) {
        float v = (lane < 8) ? sh_red[lane] : 0.0f;
        #pragma unroll
        for (int off = 4; off; off >>= 1)
            v += __shfl_xor_sync(0xffffffffu, v, off);
        if (lane == 0) y[row] = v * g_dso[row];
    }
}

// ---------------------------------------------------------------------------
// Launch sequence: quantize W_hh + W_out, 32 warmup steps, 400 step+readout.
// ---------------------------------------------------------------------------
extern "C" void kernel_launch(void* const* d_in, const int* in_sizes, int n_in,
                              void* d_out, int out_size)
{
    const float* u_hist = (const float*)d_in[0];   // [64, 512]
    const float* W_in   = (const float*)d_in[1];   // [8, 4000, 76]
    const float* W_hh   = (const float*)d_in[2];   // [8, 4000, 4000]
    const float* W_out  = (const float*)d_in[3];   // [8, 64, 8000]
    float*       out    = (float*)d_out;           // [400, 512]

    float* hbase = nullptr;
    cudaGetSymbolAddress((void**)&hbase, g_h);
    cudaMemsetAsync(hbase, 0, sizeof(float) * G * HID, 0);

    short* wq = nullptr;  cudaGetSymbolAddress((void**)&wq,  g_Wq);
    float* ds = nullptr;  cudaGetSymbolAddress((void**)&ds,  g_ds);
    short* wo = nullptr;  cudaGetSymbolAddress((void**)&wo,  g_Wo);
    float* dso = nullptr; cudaGetSymbolAddress((void**)&dso, g_dso);

    cudaFuncSetAttribute(step_kernel,
                         cudaFuncAttributeMaxDynamicSharedMemorySize, SM_TOTAL);

    quant_rows_kernel<<<NROWS / 8, 256>>>(W_hh, wq, ds, HID, KPAD);
    quant_rows_kernel<<<OROWS / 8, 256>>>(W_out, wo, dso, OWID, OWID);

    const dim3 sgrid(BXG, G);      // 144 blocks = 1/SM
    const dim3 rgrid(QG, G);       // 512 blocks

    float* hb[2] = { hbase, hbase + G * HID };

    for (int t = 0; t < EPS; ++t) {
        const float* u = u_hist + (size_t)(NHIST - EPS + t) * Q;
        step_kernel<<<sgrid, NTHREADS, SM_TOTAL>>>(W_in, u, hb[t & 1], hb[(t + 1) & 1]);
    }

    for (int s = 0; s < STEPS; ++s) {
        const float* u = (s == 0) ? (u_hist + (size_t)(NHIST - 1) * Q)
                                  : (out + (size_t)(s - 1) * Q);
        step_kernel<<<sgrid, NTHREADS, SM_TOTAL>>>(W_in, u, hb[s & 1], hb[(s + 1) & 1]);
        readout_kernel<<<rgrid, 256>>>(hb[(s + 1) & 1], out + (size_t)s * Q);
    }
}